// round 11
// baseline (speedup 1.0000x reference)
#include <cuda_runtime.h>
#include <cuda_fp16.h>
#include <cstdint>

#define BB 32
#define TT 512
#define DD 512
#define EE 8
#define HH 2048

// ---------------- device scratch (no cudaMalloc allowed) -------------------
__device__ __half g_h[(size_t)BB * TT * HH];      // h (relu'd)   64 MB
__device__ __half g_x[(size_t)BB * TT * DD];      // x as fp16    16 MB
__device__ __half g_W1t[(size_t)EE * HH * DD];    // W1^T fp16 [E][H][D] 16 MB
__device__ __half g_W2t[(size_t)EE * DD * HH];    // W2^T fp16 [E][D][H] 16 MB
__device__ float  g_part[BB * 8 * DD];
__device__ int    g_expert[BB];
__device__ int    g_ready[BB * (TT / 128)];       // h stripe-ready counters (->16)
__device__ int    g_w2done;                        // W2 transpose blocks done (->8192)

#define W2_BLOCKS ((DD / 32) * (HH / 32) * EE)     // 8192

// ---------------- helpers ---------------------------------------------------
__device__ __forceinline__ uint32_t smem_u32(const void* p) {
    uint32_t a;
    asm("{ .reg .u64 t; cvta.to.shared.u64 t, %1; cvt.u32.u64 %0, t; }" : "=r"(a) : "l"(p));
    return a;
}
#define SWZ(o) ((o) ^ ((((uint32_t)(o)) >> 3) & 0x70u))

__device__ __forceinline__ void cp_async16(uint32_t dst, const void* src) {
    asm volatile("cp.async.cg.shared.global [%0], [%1], 16;" :: "r"(dst), "l"(src));
}
__device__ __forceinline__ void cp_commit() {
    asm volatile("cp.async.commit_group;" ::: "memory");
}
__device__ __forceinline__ void cp_wait1() {
    asm volatile("cp.async.wait_group 1;" ::: "memory");
}
__device__ __forceinline__ void ldsm4(uint32_t* r, uint32_t addr) {
    asm volatile("ldmatrix.sync.aligned.m8n8.x4.shared.b16 {%0,%1,%2,%3}, [%4];"
                 : "=r"(r[0]), "=r"(r[1]), "=r"(r[2]), "=r"(r[3]) : "r"(addr));
}
__device__ __forceinline__ void mma16816(float* d, const uint32_t* a, uint32_t b0, uint32_t b1) {
    asm volatile("mma.sync.aligned.m16n8k16.row.col.f32.f16.f16.f32 "
                 "{%0,%1,%2,%3}, {%4,%5,%6,%7}, {%8,%9}, {%0,%1,%2,%3};"
                 : "+f"(d[0]), "+f"(d[1]), "+f"(d[2]), "+f"(d[3])
                 : "r"(a[0]), "r"(a[1]), "r"(a[2]), "r"(a[3]), "r"(b0), "r"(b1));
}

// ---------------- router (fused x -> fp16 convert + pooling) ----------------
__global__ void convert_pool(const float* __restrict__ x, __half2* __restrict__ xt,
                             float* __restrict__ part) {
    if (threadIdx.x == 0) cudaTriggerProgrammaticLaunchCompletion();
    int b = blockIdx.x, s = blockIdx.y, tid = threadIdx.x;   // tid: half2 index 0..255
    // reset overlap counters for this replay (later kernels are stream-ordered)
    if (b == 0 && s == 0) {
        if (tid < BB * (TT / 128)) g_ready[tid] = 0;
        if (tid == 128) g_w2done = 0;
    }
    size_t base = ((size_t)b * TT + s * 64) * DD;
    float s0 = 0.f, s1 = 0.f;
    #pragma unroll 4
    for (int t = 0; t < 64; ++t) {
        float2 v = *reinterpret_cast<const float2*>(x + base + (size_t)t * DD + 2 * tid);
        s0 += v.x; s1 += v.y;
        xt[(base + (size_t)t * DD) / 2 + tid] = __floats2half2_rn(v.x, v.y);
    }
    float2 p; p.x = s0; p.y = s1;
    *reinterpret_cast<float2*>(part + ((size_t)b * 8 + s) * DD + 2 * tid) = p;
}

__global__ void router_final(const float* __restrict__ part,
                             const float* __restrict__ Wp,
                             const float* __restrict__ bp,
                             float* __restrict__ out_tail) {
    int b = blockIdx.x, tid = threadIdx.x;
    __shared__ float pooled[DD];
    __shared__ float logits[EE];

    for (int d = tid; d < DD; d += 256) {
        float s = 0.f;
        #pragma unroll
        for (int p = 0; p < 8; ++p) s += part[((size_t)b * 8 + p) * DD + d];
        pooled[d] = s * (1.0f / TT);
    }
    __syncthreads();

    int warp = tid >> 5, lane = tid & 31;
    if (warp < EE) {
        float s = 0.f;
        for (int d = lane; d < DD; d += 32) s += pooled[d] * Wp[(size_t)d * EE + warp];
        #pragma unroll
        for (int o = 16; o > 0; o >>= 1) s += __shfl_xor_sync(0xffffffffu, s, o);
        if (lane == 0) logits[warp] = s + bp[warp];
    }
    __syncthreads();

    if (tid == 0) {
        float m = logits[0]; int arg = 0;
        #pragma unroll
        for (int e = 1; e < EE; ++e) if (logits[e] > m) { m = logits[e]; arg = e; }
        float p[EE], sum = 0.f;
        #pragma unroll
        for (int e = 0; e < EE; ++e) { p[e] = __expf(logits[e] - m); sum += p[e]; }
        float inv = 1.0f / sum;
        #pragma unroll
        for (int e = 0; e < EE; ++e) out_tail[b * EE + e] = p[e] * inv;
        out_tail[BB * EE + b] = (float)arg;
        g_expert[b] = arg;
    }
}

// ---------------- weight transpose + fp16 rounding ---------------------------
// src: [E][R][C] fp32 -> dst: [E][C][R] fp16. Grid: (C/32, R/32, E).
// done != nullptr: signal completion counter (for consumers that spin).
__global__ void transpose_w(const float* __restrict__ src, __half* __restrict__ dst,
                            int R, int C, int* done) {
    if (threadIdx.x == 0 && threadIdx.y == 0) cudaTriggerProgrammaticLaunchCompletion();
    __shared__ float tile[32][33];
    int e = blockIdx.z;
    src += (size_t)e * R * C;
    dst += (size_t)e * R * C;
    int c0 = blockIdx.x * 32, r0 = blockIdx.y * 32;
    int tx = threadIdx.x, ty = threadIdx.y;
    #pragma unroll
    for (int j = 0; j < 32; j += 8)
        tile[ty + j][tx] = src[(size_t)(r0 + ty + j) * C + c0 + tx];
    __syncthreads();
    #pragma unroll
    for (int j = 0; j < 32; j += 8)
        dst[(size_t)(c0 + ty + j) * R + r0 + tx] = __float2half_rn(tile[tx][ty + j]);
    if (done) {
        __threadfence();
        __syncthreads();
        if (tx == 0 && ty == 0) atomicAdd(done, 1);
    }
}

// ---------------- fp16 mma.sync GEMM -----------------------------------------
// C[b](TT x ND) = act(A[b](TT x KD) @ Bt[e]^T + bias[e]);  Bt: [E][ND][KD] fp16
// CTA tile 128x128, BK=64 halves, 3-stage cp.async, 8 warps 64x32, 2 CTAs/SM.
// TRIG: fire PDL trigger at start. SIGNAL: bump h stripe counter at end.
// WAIT: spin for h stripe (16 producer tiles) + W2 transpose before loading.
template <int KD, int ND, bool RELU, bool OUT_HALF, bool TRIG, bool SIGNAL, bool WAIT>
__global__ __launch_bounds__(256, 2)
void moe_gemm(const __half* __restrict__ A, const __half* __restrict__ Bt,
              const float* __restrict__ bias, void* __restrict__ Cv) {
    const int tid = threadIdx.x, wid = tid >> 5, lane = tid & 31;
    if (TRIG) {
        if (tid == 0) cudaTriggerProgrammaticLaunchCompletion();
    }
    extern __shared__ uint8_t smraw[];
    const int b = blockIdx.z;
    const int row0 = blockIdx.y * 128;
    const int col0 = blockIdx.x * 128;

    if (WAIT) {   // producer data not stream-ordered: spin on readiness flags
        if (tid == 0) {
            const int s = b * (TT / 128) + blockIdx.y;
            while (*(volatile int*)&g_ready[s] < (ND == DD ? HH / 128 : 16)) __nanosleep(64);
            while (*(volatile int*)&g_w2done < W2_BLOCKS) __nanosleep(64);
        }
        __syncthreads();
    }

    const int e = g_expert[b];
    const __half* Ab = A + (size_t)b * TT * KD;
    const __half* Bb = Bt + (size_t)e * ND * KD;
    const float* biasb = bias + (size_t)e * ND;

    const uint32_t smBase = smem_u32(smraw);
    const int lr = tid >> 3;   // loader row (0..31)
    const int lc = tid & 7;    // loader 16B chunk (0..7) -> 8 halves

    constexpr int NC = KD / 64;

    auto issue = [&](int c) {
        if (c < NC) {
            uint32_t sA = smBase + (uint32_t)(c % 3) * 32768u;
            uint32_t sB = sA + 16384u;
            int k0 = c * 64;
            #pragma unroll
            for (int i = 0; i < 4; ++i) {
                int r = lr + 32 * i;
                cp_async16(sA + SWZ((uint32_t)(r * 128 + lc * 16)),
                           Ab + (size_t)(row0 + r) * KD + k0 + lc * 8);
            }
            #pragma unroll
            for (int i = 0; i < 4; ++i) {
                int r = lr + 32 * i;
                cp_async16(sB + SWZ((uint32_t)(r * 128 + lc * 16)),
                           Bb + (size_t)(col0 + r) * KD + k0 + lc * 8);
            }
        }
        cp_commit();
    };

    issue(0);
    issue(1);

    const int wm = wid >> 2;   // 0..1
    const int wn = wid & 3;    // 0..3

    // ldmatrix lane addressing
    const int aRow = lane & 15;          // A: row within 16-row tile
    const int aColB = (lane >> 4) * 16;  // A: 16B col half (k 0-7 / 8-15)
    const int bRow = ((lane >> 4) & 1) * 8 + (lane & 7);  // B: n row within 16
    const int bColB = ((lane >> 3) & 1) * 16;             // B: k-half bytes

    float acc[4][4][4];
    #pragma unroll
    for (int mt = 0; mt < 4; ++mt)
        #pragma unroll
        for (int nt = 0; nt < 4; ++nt)
            #pragma unroll
            for (int k = 0; k < 4; ++k) acc[mt][nt][k] = 0.f;

    #pragma unroll 1
    for (int c = 0; c < NC; ++c) {
        cp_wait1();
        __syncthreads();
        issue(c + 2);

        uint32_t sA = smBase + (uint32_t)(c % 3) * 32768u;
        uint32_t sB = sA + 16384u;

        #pragma unroll
        for (int ks = 0; ks < 4; ++ks) {        // 4 x k16 per 64-half chunk
            uint32_t af[4][4];
            #pragma unroll
            for (int mt = 0; mt < 4; ++mt) {
                int row = wm * 64 + mt * 16 + aRow;
                ldsm4(af[mt], sA + SWZ((uint32_t)(row * 128 + ks * 32 + aColB)));
            }
            uint32_t bf[2][4];
            #pragma unroll
            for (int np = 0; np < 2; ++np) {
                int row = wn * 32 + np * 16 + bRow;
                ldsm4(bf[np], sB + SWZ((uint32_t)(row * 128 + ks * 32 + bColB)));
            }
            #pragma unroll
            for (int mt = 0; mt < 4; ++mt)
                #pragma unroll
                for (int nt = 0; nt < 4; ++nt) {
                    const uint32_t* bp = &bf[nt >> 1][(nt & 1) * 2];
                    mma16816(acc[mt][nt], af[mt], bp[0], bp[1]);
                }
        }
    }

    // ---------------- epilogue: bias (+relu) ----------------
    #pragma unroll
    for (int mt = 0; mt < 4; ++mt) {
        #pragma unroll
        for (int nt = 0; nt < 4; ++nt) {
            int col = col0 + wn * 32 + nt * 8 + (lane & 3) * 2;
            float bv0 = __ldg(biasb + col);
            float bv1 = __ldg(biasb + col + 1);
            #pragma unroll
            for (int h = 0; h < 2; ++h) {
                int row = row0 + wm * 64 + mt * 16 + (lane >> 2) + h * 8;
                float v0 = acc[mt][nt][h * 2 + 0] + bv0;
                float v1 = acc[mt][nt][h * 2 + 1] + bv1;
                if (RELU) { v0 = fmaxf(v0, 0.f); v1 = fmaxf(v1, 0.f); }
                if (OUT_HALF) {
                    __half2* Ch = (__half2*)((__half*)Cv + (size_t)b * TT * ND);
                    Ch[((size_t)row * ND + col) / 2] = __floats2half2_rn(v0, v1);
                } else {
                    float2 u; u.x = v0; u.y = v1;
                    *reinterpret_cast<float2*>((float*)Cv + (size_t)b * TT * ND +
                                               (size_t)row * ND + col) = u;
                }
            }
        }
    }

    if (SIGNAL) {   // publish h stripe (visible to cp.async.cg consumers via L2)
        __threadfence();
        __syncthreads();
        if (tid == 0) atomicAdd(&g_ready[b * (TT / 128) + blockIdx.y], 1);
    }
}

// ---------------- launch -----------------------------------------------------
extern "C" void kernel_launch(void* const* d_in, const int* in_sizes, int n_in,
                              void* d_out, int out_size) {
    const float* x  = (const float*)d_in[0];
    const float* Wp = (const float*)d_in[1];
    const float* bp = (const float*)d_in[2];
    const float* W1 = (const float*)d_in[3];
    const float* b1 = (const float*)d_in[4];
    const float* W2 = (const float*)d_in[5];
    const float* b2 = (const float*)d_in[6];
    float* out = (float*)d_out;

    void *pW1t, *pW2t, *pH, *pX, *pPart, *pW2done;
    cudaGetSymbolAddress(&pW1t, g_W1t);
    cudaGetSymbolAddress(&pW2t, g_W2t);
    cudaGetSymbolAddress(&pH, g_h);
    cudaGetSymbolAddress(&pX, g_x);
    cudaGetSymbolAddress(&pPart, g_part);
    cudaGetSymbolAddress(&pW2done, g_w2done);

    auto gemm1 = moe_gemm<DD, HH, true, true, true, true, false>;
    auto gemm2 = moe_gemm<HH, DD, false, false, false, false, true>;

    const int SMEM = 98304;
    cudaFuncSetAttribute(gemm1, cudaFuncAttributeMaxDynamicSharedMemorySize, SMEM);
    cudaFuncSetAttribute(gemm2, cudaFuncAttributeMaxDynamicSharedMemorySize, SMEM);
    cudaFuncSetAttribute(gemm1, cudaFuncAttributePreferredSharedMemoryCarveout, 100);
    cudaFuncSetAttribute(gemm2, cudaFuncAttributePreferredSharedMemoryCarveout, 100);

    cudaLaunchAttribute pdl[1];
    pdl[0].id = cudaLaunchAttributeProgrammaticStreamSerialization;
    pdl[0].val.programmaticStreamSerializationAllowed = 1;

    // 1) convert_pool (PDL-triggers at start; also resets overlap counters)
    convert_pool<<<dim3(BB, 8), 256>>>(x, (__half2*)pX, (float*)pPart);

    // 2) W1 transpose (PDL secondary: overlaps convert_pool)
    {
        cudaLaunchConfig_t cfg = {};
        cfg.gridDim = dim3(HH / 32, DD / 32, EE);   // C=H, R=D
        cfg.blockDim = dim3(32, 8, 1);
        cfg.attrs = pdl; cfg.numAttrs = 1;
        cudaLaunchKernelEx(&cfg, transpose_w, W1, (__half*)pW1t, DD, HH, (int*)nullptr);
    }

    // 3) router (normal: waits convert_pool + trans_W1)
    router_final<<<BB, 256>>>((const float*)pPart, Wp, bp, out + (size_t)BB * TT * DD);

    // 4) GEMM1 (PDL-triggers at start; signals per-stripe h readiness)
    gemm1<<<dim3(HH / 128, TT / 128, BB), 256, SMEM>>>(
        (const __half*)pX, (const __half*)pW1t, b1, pH);

    // 5) W2 transpose (PDL secondary: overlaps GEMM1 drain; signals g_w2done)
    {
        cudaLaunchConfig_t cfg = {};
        cfg.gridDim = dim3(DD / 32, HH / 32, EE);   // C=D, R=H
        cfg.blockDim = dim3(32, 8, 1);
        cfg.attrs = pdl; cfg.numAttrs = 1;
        cudaLaunchKernelEx(&cfg, transpose_w, W2, (__half*)pW2t, HH, DD, (int*)pW2done);
    }

    // 6) GEMM2 (PDL secondary: spins on h stripe + W2; overlaps GEMM1 tail)
    {
        cudaLaunchConfig_t cfg = {};
        cfg.gridDim = dim3(DD / 128, TT / 128, BB);
        cfg.blockDim = dim3(256, 1, 1);
        cfg.dynamicSmemBytes = SMEM;
        cfg.attrs = pdl; cfg.numAttrs = 1;
        cudaLaunchKernelEx(&cfg, gemm2,
                           (const __half*)pH, (const __half*)pW2t, b2, (void*)out);
    }
}

// round 12
// speedup vs baseline: 1.0465x; 1.0465x over previous
#include <cuda_runtime.h>
#include <cuda_fp16.h>
#include <cstdint>

#define BB 32
#define TT 512
#define DD 512
#define EE 8
#define HH 2048

// ---------------- device scratch (no cudaMalloc allowed) -------------------
__device__ __half g_h[(size_t)BB * TT * HH];      // h (relu'd)   64 MB
__device__ __half g_x[(size_t)BB * TT * DD];      // x as fp16    16 MB
__device__ __half g_W1t[(size_t)EE * HH * DD];    // W1^T fp16 [E][H][D] 16 MB
__device__ __half g_W2t[(size_t)EE * DD * HH];    // W2^T fp16 [E][D][H] 16 MB
__device__ float  g_part[BB * 8 * DD];
__device__ int    g_expert[BB];

// ---------------- helpers ---------------------------------------------------
__device__ __forceinline__ uint32_t smem_u32(const void* p) {
    uint32_t a;
    asm("{ .reg .u64 t; cvta.to.shared.u64 t, %1; cvt.u32.u64 %0, t; }" : "=r"(a) : "l"(p));
    return a;
}
#define SWZ(o) ((o) ^ ((((uint32_t)(o)) >> 3) & 0x70u))

__device__ __forceinline__ void cp_async16(uint32_t dst, const void* src) {
    asm volatile("cp.async.cg.shared.global [%0], [%1], 16;" :: "r"(dst), "l"(src));
}
__device__ __forceinline__ void cp_commit() {
    asm volatile("cp.async.commit_group;" ::: "memory");
}
__device__ __forceinline__ void cp_wait1() {
    asm volatile("cp.async.wait_group 1;" ::: "memory");
}
__device__ __forceinline__ void ldsm4(uint32_t* r, uint32_t addr) {
    asm volatile("ldmatrix.sync.aligned.m8n8.x4.shared.b16 {%0,%1,%2,%3}, [%4];"
                 : "=r"(r[0]), "=r"(r[1]), "=r"(r[2]), "=r"(r[3]) : "r"(addr));
}
__device__ __forceinline__ void mma16816(float* d, const uint32_t* a, uint32_t b0, uint32_t b1) {
    asm volatile("mma.sync.aligned.m16n8k16.row.col.f32.f16.f16.f32 "
                 "{%0,%1,%2,%3}, {%4,%5,%6,%7}, {%8,%9}, {%0,%1,%2,%3};"
                 : "+f"(d[0]), "+f"(d[1]), "+f"(d[2]), "+f"(d[3])
                 : "r"(a[0]), "r"(a[1]), "r"(a[2]), "r"(a[3]), "r"(b0), "r"(b1));
}

// ---------------- router (fused x -> fp16 convert + pooling) ----------------
__global__ void convert_pool(const float* __restrict__ x, __half2* __restrict__ xt,
                             float* __restrict__ part) {
    if (threadIdx.x == 0) cudaTriggerProgrammaticLaunchCompletion();
    int b = blockIdx.x, s = blockIdx.y, tid = threadIdx.x;   // tid: half2 index 0..255
    size_t base = ((size_t)b * TT + s * 64) * DD;
    float s0 = 0.f, s1 = 0.f;
    #pragma unroll 4
    for (int t = 0; t < 64; ++t) {
        float2 v = *reinterpret_cast<const float2*>(x + base + (size_t)t * DD + 2 * tid);
        s0 += v.x; s1 += v.y;
        xt[(base + (size_t)t * DD) / 2 + tid] = __floats2half2_rn(v.x, v.y);
    }
    float2 p; p.x = s0; p.y = s1;
    *reinterpret_cast<float2*>(part + ((size_t)b * 8 + s) * DD + 2 * tid) = p;
}

__global__ void router_final(const float* __restrict__ part,
                             const float* __restrict__ Wp,
                             const float* __restrict__ bp,
                             float* __restrict__ out_tail) {
    int b = blockIdx.x, tid = threadIdx.x;
    __shared__ float pooled[DD];
    __shared__ float logits[EE];

    for (int d = tid; d < DD; d += 256) {
        float s = 0.f;
        #pragma unroll
        for (int p = 0; p < 8; ++p) s += part[((size_t)b * 8 + p) * DD + d];
        pooled[d] = s * (1.0f / TT);
    }
    __syncthreads();

    int warp = tid >> 5, lane = tid & 31;
    if (warp < EE) {
        float s = 0.f;
        for (int d = lane; d < DD; d += 32) s += pooled[d] * Wp[(size_t)d * EE + warp];
        #pragma unroll
        for (int o = 16; o > 0; o >>= 1) s += __shfl_xor_sync(0xffffffffu, s, o);
        if (lane == 0) logits[warp] = s + bp[warp];
    }
    __syncthreads();

    if (tid == 0) {
        float m = logits[0]; int arg = 0;
        #pragma unroll
        for (int e = 1; e < EE; ++e) if (logits[e] > m) { m = logits[e]; arg = e; }
        float p[EE], sum = 0.f;
        #pragma unroll
        for (int e = 0; e < EE; ++e) { p[e] = __expf(logits[e] - m); sum += p[e]; }
        float inv = 1.0f / sum;
        #pragma unroll
        for (int e = 0; e < EE; ++e) out_tail[b * EE + e] = p[e] * inv;
        out_tail[BB * EE + b] = (float)arg;
        g_expert[b] = arg;
    }
}

// ---------------- weight transpose + fp16 rounding ---------------------------
// src: [E][R][C] fp32 -> dst: [E][C][R] fp16. Grid: (C/32, R/32, E).
__global__ void transpose_w(const float* __restrict__ src, __half* __restrict__ dst,
                            int R, int C) {
    if (threadIdx.x == 0 && threadIdx.y == 0) cudaTriggerProgrammaticLaunchCompletion();
    __shared__ float tile[32][33];
    int e = blockIdx.z;
    src += (size_t)e * R * C;
    dst += (size_t)e * R * C;
    int c0 = blockIdx.x * 32, r0 = blockIdx.y * 32;
    int tx = threadIdx.x, ty = threadIdx.y;
    #pragma unroll
    for (int j = 0; j < 32; j += 8)
        tile[ty + j][tx] = src[(size_t)(r0 + ty + j) * C + c0 + tx];
    __syncthreads();
    #pragma unroll
    for (int j = 0; j < 32; j += 8)
        dst[(size_t)(c0 + ty + j) * R + r0 + tx] = __float2half_rn(tile[tx][ty + j]);
}

// ---------------- fp16 mma.sync GEMM -----------------------------------------
// C[b](TT x ND) = act(A[b](TT x KD) @ Bt[e]^T + bias[e]);  Bt: [E][ND][KD] fp16
// CTA tile 128x128, BK=64 halves, 3-stage cp.async, 8 warps 64x32, 2 CTAs/SM.
// TRIG: fire PDL trigger at block start. GDS: grid-dep-sync (PDL secondary).
template <int KD, int ND, bool RELU, bool OUT_HALF, bool TRIG, bool GDS>
__global__ __launch_bounds__(256, 2)
void moe_gemm(const __half* __restrict__ A, const __half* __restrict__ Bt,
              const float* __restrict__ bias, void* __restrict__ Cv) {
    const int tid = threadIdx.x, wid = tid >> 5, lane = tid & 31;
    if (GDS) {
        cudaGridDependencySynchronize();   // park until ALL prior grids complete
    } else if (TRIG) {
        if (tid == 0) cudaTriggerProgrammaticLaunchCompletion();
    }
    extern __shared__ uint8_t smraw[];
    const int b = blockIdx.z;
    const int e = g_expert[b];
    const int row0 = blockIdx.y * 128;
    const int col0 = blockIdx.x * 128;

    const __half* Ab = A + (size_t)b * TT * KD;
    const __half* Bb = Bt + (size_t)e * ND * KD;
    const float* biasb = bias + (size_t)e * ND;

    const uint32_t smBase = smem_u32(smraw);
    const int lr = tid >> 3;   // loader row (0..31)
    const int lc = tid & 7;    // loader 16B chunk (0..7) -> 8 halves

    constexpr int NC = KD / 64;

    auto issue = [&](int c) {
        if (c < NC) {
            uint32_t sA = smBase + (uint32_t)(c % 3) * 32768u;
            uint32_t sB = sA + 16384u;
            int k0 = c * 64;
            #pragma unroll
            for (int i = 0; i < 4; ++i) {
                int r = lr + 32 * i;
                cp_async16(sA + SWZ((uint32_t)(r * 128 + lc * 16)),
                           Ab + (size_t)(row0 + r) * KD + k0 + lc * 8);
            }
            #pragma unroll
            for (int i = 0; i < 4; ++i) {
                int r = lr + 32 * i;
                cp_async16(sB + SWZ((uint32_t)(r * 128 + lc * 16)),
                           Bb + (size_t)(col0 + r) * KD + k0 + lc * 8);
            }
        }
        cp_commit();
    };

    issue(0);
    issue(1);

    const int wm = wid >> 2;   // 0..1
    const int wn = wid & 3;    // 0..3

    // ldmatrix lane addressing
    const int aRow = lane & 15;          // A: row within 16-row tile
    const int aColB = (lane >> 4) * 16;  // A: 16B col half (k 0-7 / 8-15)
    const int bRow = ((lane >> 4) & 1) * 8 + (lane & 7);  // B: n row within 16
    const int bColB = ((lane >> 3) & 1) * 16;             // B: k-half bytes

    float acc[4][4][4];
    #pragma unroll
    for (int mt = 0; mt < 4; ++mt)
        #pragma unroll
        for (int nt = 0; nt < 4; ++nt)
            #pragma unroll
            for (int k = 0; k < 4; ++k) acc[mt][nt][k] = 0.f;

    #pragma unroll 1
    for (int c = 0; c < NC; ++c) {
        cp_wait1();
        __syncthreads();
        issue(c + 2);

        uint32_t sA = smBase + (uint32_t)(c % 3) * 32768u;
        uint32_t sB = sA + 16384u;

        #pragma unroll
        for (int ks = 0; ks < 4; ++ks) {        // 4 x k16 per 64-half chunk
            uint32_t af[4][4];
            #pragma unroll
            for (int mt = 0; mt < 4; ++mt) {
                int row = wm * 64 + mt * 16 + aRow;
                ldsm4(af[mt], sA + SWZ((uint32_t)(row * 128 + ks * 32 + aColB)));
            }
            uint32_t bf[2][4];
            #pragma unroll
            for (int np = 0; np < 2; ++np) {
                int row = wn * 32 + np * 16 + bRow;
                ldsm4(bf[np], sB + SWZ((uint32_t)(row * 128 + ks * 32 + bColB)));
            }
            #pragma unroll
            for (int mt = 0; mt < 4; ++mt)
                #pragma unroll
                for (int nt = 0; nt < 4; ++nt) {
                    const uint32_t* bp = &bf[nt >> 1][(nt & 1) * 2];
                    mma16816(acc[mt][nt], af[mt], bp[0], bp[1]);
                }
        }
    }

    // ---------------- epilogue: bias (+relu) ----------------
    #pragma unroll
    for (int mt = 0; mt < 4; ++mt) {
        #pragma unroll
        for (int nt = 0; nt < 4; ++nt) {
            int col = col0 + wn * 32 + nt * 8 + (lane & 3) * 2;
            float bv0 = __ldg(biasb + col);
            float bv1 = __ldg(biasb + col + 1);
            #pragma unroll
            for (int h = 0; h < 2; ++h) {
                int row = row0 + wm * 64 + mt * 16 + (lane >> 2) + h * 8;
                float v0 = acc[mt][nt][h * 2 + 0] + bv0;
                float v1 = acc[mt][nt][h * 2 + 1] + bv1;
                if (RELU) { v0 = fmaxf(v0, 0.f); v1 = fmaxf(v1, 0.f); }
                if (OUT_HALF) {
                    __half2* Ch = (__half2*)((__half*)Cv + (size_t)b * TT * ND);
                    Ch[((size_t)row * ND + col) / 2] = __floats2half2_rn(v0, v1);
                } else {
                    float2 u; u.x = v0; u.y = v1;
                    *reinterpret_cast<float2*>((float*)Cv + (size_t)b * TT * ND +
                                               (size_t)row * ND + col) = u;
                }
            }
        }
    }
}

// ---------------- launch -----------------------------------------------------
extern "C" void kernel_launch(void* const* d_in, const int* in_sizes, int n_in,
                              void* d_out, int out_size) {
    const float* x  = (const float*)d_in[0];
    const float* Wp = (const float*)d_in[1];
    const float* bp = (const float*)d_in[2];
    const float* W1 = (const float*)d_in[3];
    const float* b1 = (const float*)d_in[4];
    const float* W2 = (const float*)d_in[5];
    const float* b2 = (const float*)d_in[6];
    float* out = (float*)d_out;

    void *pW1t, *pW2t, *pH, *pX, *pPart;
    cudaGetSymbolAddress(&pW1t, g_W1t);
    cudaGetSymbolAddress(&pW2t, g_W2t);
    cudaGetSymbolAddress(&pH, g_h);
    cudaGetSymbolAddress(&pX, g_x);
    cudaGetSymbolAddress(&pPart, g_part);

    auto gemm1 = moe_gemm<DD, HH, true, true, true, false>;
    auto gemm2 = moe_gemm<HH, DD, false, false, false, true>;

    const int SMEM = 98304;
    cudaFuncSetAttribute(gemm1, cudaFuncAttributeMaxDynamicSharedMemorySize, SMEM);
    cudaFuncSetAttribute(gemm2, cudaFuncAttributeMaxDynamicSharedMemorySize, SMEM);
    cudaFuncSetAttribute(gemm1, cudaFuncAttributePreferredSharedMemoryCarveout, 100);
    cudaFuncSetAttribute(gemm2, cudaFuncAttributePreferredSharedMemoryCarveout, 100);

    cudaLaunchAttribute pdl[1];
    pdl[0].id = cudaLaunchAttributeProgrammaticStreamSerialization;
    pdl[0].val.programmaticStreamSerializationAllowed = 1;

    // 1) convert_pool (PDL-triggers at start so trans_W1 overlaps it)
    convert_pool<<<dim3(BB, 8), 256>>>(x, (__half2*)pX, (float*)pPart);

    // 2) W1 transpose (PDL secondary: overlaps convert_pool)
    {
        cudaLaunchConfig_t cfg = {};
        cfg.gridDim = dim3(HH / 32, DD / 32, EE);   // C=H, R=D
        cfg.blockDim = dim3(32, 8, 1);
        cfg.attrs = pdl; cfg.numAttrs = 1;
        cudaLaunchKernelEx(&cfg, transpose_w, W1, (__half*)pW1t, DD, HH);
    }

    // 3) router (normal: waits convert_pool + trans_W1)
    router_final<<<BB, 256>>>((const float*)pPart, Wp, bp, out + (size_t)BB * TT * DD);

    // 4) GEMM1 (PDL-triggers at start so trans_W2 overlaps it)
    gemm1<<<dim3(HH / 128, TT / 128, BB), 256, SMEM>>>(
        (const __half*)pX, (const __half*)pW1t, b1, pH);

    // 5) W2 transpose (PDL secondary: runs CONCURRENTLY with tensor-bound GEMM1;
    //    itself PDL-triggers at start so GEMM2 can prelaunch)
    {
        cudaLaunchConfig_t cfg = {};
        cfg.gridDim = dim3(DD / 32, HH / 32, EE);   // C=D, R=H
        cfg.blockDim = dim3(32, 8, 1);
        cfg.attrs = pdl; cfg.numAttrs = 1;
        cudaLaunchKernelEx(&cfg, transpose_w, W2, (__half*)pW2t, HH, DD);
    }

    // 6) GEMM2 (PDL secondary with grid-dep-sync: CTAs prelaunch into slots
    //    during GEMM1/trans_W2 drain, start the instant dependencies resolve)
    {
        cudaLaunchConfig_t cfg = {};
        cfg.gridDim = dim3(DD / 128, TT / 128, BB);
        cfg.blockDim = dim3(256, 1, 1);
        cfg.dynamicSmemBytes = SMEM;
        cfg.attrs = pdl; cfg.numAttrs = 1;
        cudaLaunchKernelEx(&cfg, gemm2,
                           (const __half*)pH, (const __half*)pW2t, b2, (void*)out);
    }
}

// round 13
// speedup vs baseline: 1.0623x; 1.0152x over previous
#include <cuda_runtime.h>
#include <cuda_fp16.h>
#include <cstdint>

#define BB 32
#define TT 512
#define DD 512
#define EE 8
#define HH 2048

// ---------------- device scratch (no cudaMalloc allowed) -------------------
__device__ __half g_h[(size_t)BB * TT * HH];      // h (relu'd)   64 MB
__device__ __half g_x[(size_t)BB * TT * DD];      // x as fp16    16 MB
__device__ __half g_W1t[(size_t)EE * HH * DD];    // W1^T fp16 [E][H][D] 16 MB
__device__ __half g_W2t[(size_t)EE * DD * HH];    // W2^T fp16 [E][D][H] 16 MB
__device__ float  g_part[BB * 16 * DD];
__device__ int    g_expert[BB];

// ---------------- helpers ---------------------------------------------------
__device__ __forceinline__ uint32_t smem_u32(const void* p) {
    uint32_t a;
    asm("{ .reg .u64 t; cvta.to.shared.u64 t, %1; cvt.u32.u64 %0, t; }" : "=r"(a) : "l"(p));
    return a;
}
#define SWZ(o) ((o) ^ ((((uint32_t)(o)) >> 3) & 0x70u))

__device__ __forceinline__ void cp_async16(uint32_t dst, const void* src) {
    asm volatile("cp.async.cg.shared.global [%0], [%1], 16;" :: "r"(dst), "l"(src));
}
__device__ __forceinline__ void cp_commit() {
    asm volatile("cp.async.commit_group;" ::: "memory");
}
__device__ __forceinline__ void cp_wait1() {
    asm volatile("cp.async.wait_group 1;" ::: "memory");
}
__device__ __forceinline__ void ldsm4(uint32_t* r, uint32_t addr) {
    asm volatile("ldmatrix.sync.aligned.m8n8.x4.shared.b16 {%0,%1,%2,%3}, [%4];"
                 : "=r"(r[0]), "=r"(r[1]), "=r"(r[2]), "=r"(r[3]) : "r"(addr));
}
__device__ __forceinline__ void mma16816(float* d, const uint32_t* a, uint32_t b0, uint32_t b1) {
    asm volatile("mma.sync.aligned.m16n8k16.row.col.f32.f16.f16.f32 "
                 "{%0,%1,%2,%3}, {%4,%5,%6,%7}, {%8,%9}, {%0,%1,%2,%3};"
                 : "+f"(d[0]), "+f"(d[1]), "+f"(d[2]), "+f"(d[3])
                 : "r"(a[0]), "r"(a[1]), "r"(a[2]), "r"(a[3]), "r"(b0), "r"(b1));
}

// ---------------- router (fused x -> fp16 convert + pooling) ----------------
// 512 CTAs (BB x 16), 32 rows each: ~2x memory parallelism vs 256-CTA version.
__global__ void convert_pool(const float* __restrict__ x, __half2* __restrict__ xt,
                             float* __restrict__ part) {
    if (threadIdx.x == 0) cudaTriggerProgrammaticLaunchCompletion();
    int b = blockIdx.x, s = blockIdx.y, tid = threadIdx.x;   // tid: half2 index 0..255
    size_t base = ((size_t)b * TT + s * 32) * DD;
    float s0 = 0.f, s1 = 0.f;
    #pragma unroll 4
    for (int t = 0; t < 32; ++t) {
        float2 v = *reinterpret_cast<const float2*>(x + base + (size_t)t * DD + 2 * tid);
        s0 += v.x; s1 += v.y;
        xt[(base + (size_t)t * DD) / 2 + tid] = __floats2half2_rn(v.x, v.y);
    }
    float2 p; p.x = s0; p.y = s1;
    *reinterpret_cast<float2*>(part + ((size_t)b * 16 + s) * DD + 2 * tid) = p;
}

__global__ void router_final(const float* __restrict__ part,
                             const float* __restrict__ Wp,
                             const float* __restrict__ bp,
                             float* __restrict__ out_tail) {
    if (threadIdx.x == 0) cudaTriggerProgrammaticLaunchCompletion();  // let GEMM1 prelaunch
    int b = blockIdx.x, tid = threadIdx.x;
    __shared__ float pooled[DD];
    __shared__ float logits[EE];

    for (int d = tid; d < DD; d += 256) {
        float s = 0.f;
        #pragma unroll
        for (int p = 0; p < 16; ++p) s += part[((size_t)b * 16 + p) * DD + d];
        pooled[d] = s * (1.0f / TT);
    }
    __syncthreads();

    int warp = tid >> 5, lane = tid & 31;
    if (warp < EE) {
        float s = 0.f;
        for (int d = lane; d < DD; d += 32) s += pooled[d] * Wp[(size_t)d * EE + warp];
        #pragma unroll
        for (int o = 16; o > 0; o >>= 1) s += __shfl_xor_sync(0xffffffffu, s, o);
        if (lane == 0) logits[warp] = s + bp[warp];
    }
    __syncthreads();

    if (tid == 0) {
        float m = logits[0]; int arg = 0;
        #pragma unroll
        for (int e = 1; e < EE; ++e) if (logits[e] > m) { m = logits[e]; arg = e; }
        float p[EE], sum = 0.f;
        #pragma unroll
        for (int e = 0; e < EE; ++e) { p[e] = __expf(logits[e] - m); sum += p[e]; }
        float inv = 1.0f / sum;
        #pragma unroll
        for (int e = 0; e < EE; ++e) out_tail[b * EE + e] = p[e] * inv;
        out_tail[BB * EE + b] = (float)arg;
        g_expert[b] = arg;
    }
}

// ---------------- weight transpose + fp16 rounding ---------------------------
// src: [E][R][C] fp32 -> dst: [E][C][R] fp16. Grid: (C/32, R/32, E).
__global__ void transpose_w(const float* __restrict__ src, __half* __restrict__ dst,
                            int R, int C) {
    if (threadIdx.x == 0 && threadIdx.y == 0) cudaTriggerProgrammaticLaunchCompletion();
    __shared__ float tile[32][33];
    int e = blockIdx.z;
    src += (size_t)e * R * C;
    dst += (size_t)e * R * C;
    int c0 = blockIdx.x * 32, r0 = blockIdx.y * 32;
    int tx = threadIdx.x, ty = threadIdx.y;
    #pragma unroll
    for (int j = 0; j < 32; j += 8)
        tile[ty + j][tx] = src[(size_t)(r0 + ty + j) * C + c0 + tx];
    __syncthreads();
    #pragma unroll
    for (int j = 0; j < 32; j += 8)
        dst[(size_t)(c0 + ty + j) * R + r0 + tx] = __float2half_rn(tile[tx][ty + j]);
}

// ---------------- fp16 mma.sync GEMM -----------------------------------------
// C[b](TT x ND) = act(A[b](TT x KD) @ Bt[e]^T + bias[e]);  Bt: [E][ND][KD] fp16
// CTA tile 128x128, BK=64 halves, 3-stage cp.async, 8 warps 64x32, 2 CTAs/SM.
// TRIG: fire PDL trigger at block start. GDS: grid-dep-sync first (PDL secondary).
template <int KD, int ND, bool RELU, bool OUT_HALF, bool TRIG, bool GDS>
__global__ __launch_bounds__(256, 2)
void moe_gemm(const __half* __restrict__ A, const __half* __restrict__ Bt,
              const float* __restrict__ bias, void* __restrict__ Cv) {
    const int tid = threadIdx.x, wid = tid >> 5, lane = tid & 31;
    if (GDS) cudaGridDependencySynchronize();   // prelaunched; wait priors done
    if (TRIG) {
        if (tid == 0) cudaTriggerProgrammaticLaunchCompletion();
    }
    extern __shared__ uint8_t smraw[];
    const int b = blockIdx.z;
    const int e = g_expert[b];
    const int row0 = blockIdx.y * 128;
    const int col0 = blockIdx.x * 128;

    const __half* Ab = A + (size_t)b * TT * KD;
    const __half* Bb = Bt + (size_t)e * ND * KD;
    const float* biasb = bias + (size_t)e * ND;

    const uint32_t smBase = smem_u32(smraw);
    const int lr = tid >> 3;   // loader row (0..31)
    const int lc = tid & 7;    // loader 16B chunk (0..7) -> 8 halves

    constexpr int NC = KD / 64;

    auto issue = [&](int c) {
        if (c < NC) {
            uint32_t sA = smBase + (uint32_t)(c % 3) * 32768u;
            uint32_t sB = sA + 16384u;
            int k0 = c * 64;
            #pragma unroll
            for (int i = 0; i < 4; ++i) {
                int r = lr + 32 * i;
                cp_async16(sA + SWZ((uint32_t)(r * 128 + lc * 16)),
                           Ab + (size_t)(row0 + r) * KD + k0 + lc * 8);
            }
            #pragma unroll
            for (int i = 0; i < 4; ++i) {
                int r = lr + 32 * i;
                cp_async16(sB + SWZ((uint32_t)(r * 128 + lc * 16)),
                           Bb + (size_t)(col0 + r) * KD + k0 + lc * 8);
            }
        }
        cp_commit();
    };

    issue(0);
    issue(1);

    const int wm = wid >> 2;   // 0..1
    const int wn = wid & 3;    // 0..3

    // ldmatrix lane addressing
    const int aRow = lane & 15;          // A: row within 16-row tile
    const int aColB = (lane >> 4) * 16;  // A: 16B col half (k 0-7 / 8-15)
    const int bRow = ((lane >> 4) & 1) * 8 + (lane & 7);  // B: n row within 16
    const int bColB = ((lane >> 3) & 1) * 16;             // B: k-half bytes

    float acc[4][4][4];
    #pragma unroll
    for (int mt = 0; mt < 4; ++mt)
        #pragma unroll
        for (int nt = 0; nt < 4; ++nt)
            #pragma unroll
            for (int k = 0; k < 4; ++k) acc[mt][nt][k] = 0.f;

    #pragma unroll 1
    for (int c = 0; c < NC; ++c) {
        cp_wait1();
        __syncthreads();
        issue(c + 2);

        uint32_t sA = smBase + (uint32_t)(c % 3) * 32768u;
        uint32_t sB = sA + 16384u;

        #pragma unroll
        for (int ks = 0; ks < 4; ++ks) {        // 4 x k16 per 64-half chunk
            uint32_t af[4][4];
            #pragma unroll
            for (int mt = 0; mt < 4; ++mt) {
                int row = wm * 64 + mt * 16 + aRow;
                ldsm4(af[mt], sA + SWZ((uint32_t)(row * 128 + ks * 32 + aColB)));
            }
            uint32_t bf[2][4];
            #pragma unroll
            for (int np = 0; np < 2; ++np) {
                int row = wn * 32 + np * 16 + bRow;
                ldsm4(bf[np], sB + SWZ((uint32_t)(row * 128 + ks * 32 + bColB)));
            }
            #pragma unroll
            for (int mt = 0; mt < 4; ++mt)
                #pragma unroll
                for (int nt = 0; nt < 4; ++nt) {
                    const uint32_t* bp = &bf[nt >> 1][(nt & 1) * 2];
                    mma16816(acc[mt][nt], af[mt], bp[0], bp[1]);
                }
        }
    }

    // ---------------- epilogue: bias (+relu) ----------------
    #pragma unroll
    for (int mt = 0; mt < 4; ++mt) {
        #pragma unroll
        for (int nt = 0; nt < 4; ++nt) {
            int col = col0 + wn * 32 + nt * 8 + (lane & 3) * 2;
            float bv0 = __ldg(biasb + col);
            float bv1 = __ldg(biasb + col + 1);
            #pragma unroll
            for (int h = 0; h < 2; ++h) {
                int row = row0 + wm * 64 + mt * 16 + (lane >> 2) + h * 8;
                float v0 = acc[mt][nt][h * 2 + 0] + bv0;
                float v1 = acc[mt][nt][h * 2 + 1] + bv1;
                if (RELU) { v0 = fmaxf(v0, 0.f); v1 = fmaxf(v1, 0.f); }
                if (OUT_HALF) {
                    __half2* Ch = (__half2*)((__half*)Cv + (size_t)b * TT * ND);
                    Ch[((size_t)row * ND + col) / 2] = __floats2half2_rn(v0, v1);
                } else {
                    float2 u; u.x = v0; u.y = v1;
                    *reinterpret_cast<float2*>((float*)Cv + (size_t)b * TT * ND +
                                               (size_t)row * ND + col) = u;
                }
            }
        }
    }
}

// ---------------- launch -----------------------------------------------------
extern "C" void kernel_launch(void* const* d_in, const int* in_sizes, int n_in,
                              void* d_out, int out_size) {
    const float* x  = (const float*)d_in[0];
    const float* Wp = (const float*)d_in[1];
    const float* bp = (const float*)d_in[2];
    const float* W1 = (const float*)d_in[3];
    const float* b1 = (const float*)d_in[4];
    const float* W2 = (const float*)d_in[5];
    const float* b2 = (const float*)d_in[6];
    float* out = (float*)d_out;

    void *pW1t, *pW2t, *pH, *pX, *pPart;
    cudaGetSymbolAddress(&pW1t, g_W1t);
    cudaGetSymbolAddress(&pW2t, g_W2t);
    cudaGetSymbolAddress(&pH, g_h);
    cudaGetSymbolAddress(&pX, g_x);
    cudaGetSymbolAddress(&pPart, g_part);

    auto gemm1 = moe_gemm<DD, HH, true, true, true, true>;    // GDS + trigger
    auto gemm2 = moe_gemm<HH, DD, false, false, false, false>; // plain (R10 style)

    const int SMEM = 98304;
    cudaFuncSetAttribute(gemm1, cudaFuncAttributeMaxDynamicSharedMemorySize, SMEM);
    cudaFuncSetAttribute(gemm2, cudaFuncAttributeMaxDynamicSharedMemorySize, SMEM);
    cudaFuncSetAttribute(gemm1, cudaFuncAttributePreferredSharedMemoryCarveout, 100);
    cudaFuncSetAttribute(gemm2, cudaFuncAttributePreferredSharedMemoryCarveout, 100);

    cudaLaunchAttribute pdl[1];
    pdl[0].id = cudaLaunchAttributeProgrammaticStreamSerialization;
    pdl[0].val.programmaticStreamSerializationAllowed = 1;

    // 1) convert_pool, 512 CTAs (PDL-triggers at start so trans_W1 overlaps it)
    convert_pool<<<dim3(BB, 16), 256>>>(x, (__half2*)pX, (float*)pPart);

    // 2) W1 transpose (PDL secondary: overlaps convert_pool)
    {
        cudaLaunchConfig_t cfg = {};
        cfg.gridDim = dim3(HH / 32, DD / 32, EE);   // C=H, R=D
        cfg.blockDim = dim3(32, 8, 1);
        cfg.attrs = pdl; cfg.numAttrs = 1;
        cudaLaunchKernelEx(&cfg, transpose_w, W1, (__half*)pW1t, DD, HH);
    }

    // 3) router (normal: waits convert_pool + trans_W1; triggers at start so
    //    GEMM1 prelaunches during its ~3us)
    router_final<<<BB, 256>>>((const float*)pPart, Wp, bp, out + (size_t)BB * TT * DD);

    // 4) GEMM1 (PDL secondary + GDS: CTAs staged during router, start instantly
    //    when g_expert is final; triggers at start so trans_W2 overlaps it)
    {
        cudaLaunchConfig_t cfg = {};
        cfg.gridDim = dim3(HH / 128, TT / 128, BB);
        cfg.blockDim = dim3(256, 1, 1);
        cfg.dynamicSmemBytes = SMEM;
        cfg.attrs = pdl; cfg.numAttrs = 1;
        cudaLaunchKernelEx(&cfg, gemm1,
                           (const __half*)pX, (const __half*)pW1t, b1, (void*)pH);
    }

    // 5) W2 transpose (PDL secondary: runs CONCURRENTLY with tensor-bound GEMM1)
    {
        cudaLaunchConfig_t cfg = {};
        cfg.gridDim = dim3(DD / 32, HH / 32, EE);   // C=D, R=H
        cfg.blockDim = dim3(32, 8, 1);
        cfg.attrs = pdl; cfg.numAttrs = 1;
        cudaLaunchKernelEx(&cfg, transpose_w, W2, (__half*)pW2t, HH, DD);
    }

    // 6) GEMM2 (normal: waits GEMM1 + trans_W2) — R10's best-known arrangement
    gemm2<<<dim3(DD / 128, TT / 128, BB), 256, SMEM>>>(
        (const __half*)pH, (const __half*)pW2t, b2, (void*)out);
}

// round 14
// speedup vs baseline: 1.0742x; 1.0112x over previous
#include <cuda_runtime.h>
#include <cuda_fp16.h>
#include <cstdint>

#define BB 32
#define TT 512
#define DD 512
#define EE 8
#define HH 2048

// ---------------- device scratch (no cudaMalloc allowed) -------------------
__device__ __half g_h[(size_t)BB * TT * HH];      // h (relu'd)   64 MB
__device__ __half g_x[(size_t)BB * TT * DD];      // x as fp16    16 MB
__device__ __half g_W1t[(size_t)EE * HH * DD];    // W1^T fp16 [E][H][D] 16 MB
__device__ __half g_W2t[(size_t)EE * DD * HH];    // W2^T fp16 [E][D][H] 16 MB
__device__ float  g_part[BB * 16 * DD];
__device__ int    g_expert[BB];

// ---------------- helpers ---------------------------------------------------
__device__ __forceinline__ uint32_t smem_u32(const void* p) {
    uint32_t a;
    asm("{ .reg .u64 t; cvta.to.shared.u64 t, %1; cvt.u32.u64 %0, t; }" : "=r"(a) : "l"(p));
    return a;
}
#define SWZ(o) ((o) ^ ((((uint32_t)(o)) >> 3) & 0x70u))

__device__ __forceinline__ void cp_async16(uint32_t dst, const void* src) {
    asm volatile("cp.async.cg.shared.global [%0], [%1], 16;" :: "r"(dst), "l"(src));
}
__device__ __forceinline__ void cp_commit() {
    asm volatile("cp.async.commit_group;" ::: "memory");
}
__device__ __forceinline__ void cp_wait1() {
    asm volatile("cp.async.wait_group 1;" ::: "memory");
}
__device__ __forceinline__ void ldsm4(uint32_t* r, uint32_t addr) {
    asm volatile("ldmatrix.sync.aligned.m8n8.x4.shared.b16 {%0,%1,%2,%3}, [%4];"
                 : "=r"(r[0]), "=r"(r[1]), "=r"(r[2]), "=r"(r[3]) : "r"(addr));
}
__device__ __forceinline__ void mma16816(float* d, const uint32_t* a, uint32_t b0, uint32_t b1) {
    asm volatile("mma.sync.aligned.m16n8k16.row.col.f32.f16.f16.f32 "
                 "{%0,%1,%2,%3}, {%4,%5,%6,%7}, {%8,%9}, {%0,%1,%2,%3};"
                 : "+f"(d[0]), "+f"(d[1]), "+f"(d[2]), "+f"(d[3])
                 : "r"(a[0]), "r"(a[1]), "r"(a[2]), "r"(a[3]), "r"(b0), "r"(b1));
}

// ---------------- router (fused x -> fp16 convert + pooling) ----------------
// 512 CTAs (BB x 16), 32 rows each.
__global__ void convert_pool(const float* __restrict__ x, __half2* __restrict__ xt,
                             float* __restrict__ part) {
    if (threadIdx.x == 0) cudaTriggerProgrammaticLaunchCompletion();
    int b = blockIdx.x, s = blockIdx.y, tid = threadIdx.x;   // tid: half2 index 0..255
    size_t base = ((size_t)b * TT + s * 32) * DD;
    float s0 = 0.f, s1 = 0.f;
    #pragma unroll 4
    for (int t = 0; t < 32; ++t) {
        float2 v = *reinterpret_cast<const float2*>(x + base + (size_t)t * DD + 2 * tid);
        s0 += v.x; s1 += v.y;
        xt[(base + (size_t)t * DD) / 2 + tid] = __floats2half2_rn(v.x, v.y);
    }
    float2 p; p.x = s0; p.y = s1;
    *reinterpret_cast<float2*>(part + ((size_t)b * 16 + s) * DD + 2 * tid) = p;
}

__global__ void router_final(const float* __restrict__ part,
                             const float* __restrict__ Wp,
                             const float* __restrict__ bp,
                             float* __restrict__ out_tail) {
    cudaGridDependencySynchronize();   // PDL secondary: prelaunched during convert
    if (threadIdx.x == 0) cudaTriggerProgrammaticLaunchCompletion();  // GEMM1 prelaunch
    int b = blockIdx.x, tid = threadIdx.x;
    __shared__ float pooled[DD];
    __shared__ float logits[EE];

    for (int d = tid; d < DD; d += 256) {
        float s = 0.f;
        #pragma unroll
        for (int p = 0; p < 16; ++p) s += part[((size_t)b * 16 + p) * DD + d];
        pooled[d] = s * (1.0f / TT);
    }
    __syncthreads();

    int warp = tid >> 5, lane = tid & 31;
    if (warp < EE) {
        float s = 0.f;
        for (int d = lane; d < DD; d += 32) s += pooled[d] * Wp[(size_t)d * EE + warp];
        #pragma unroll
        for (int o = 16; o > 0; o >>= 1) s += __shfl_xor_sync(0xffffffffu, s, o);
        if (lane == 0) logits[warp] = s + bp[warp];
    }
    __syncthreads();

    if (tid == 0) {
        float m = logits[0]; int arg = 0;
        #pragma unroll
        for (int e = 1; e < EE; ++e) if (logits[e] > m) { m = logits[e]; arg = e; }
        float p[EE], sum = 0.f;
        #pragma unroll
        for (int e = 0; e < EE; ++e) { p[e] = __expf(logits[e] - m); sum += p[e]; }
        float inv = 1.0f / sum;
        #pragma unroll
        for (int e = 0; e < EE; ++e) out_tail[b * EE + e] = p[e] * inv;
        out_tail[BB * EE + b] = (float)arg;
        g_expert[b] = arg;
    }
}

// ---------------- weight transpose + fp16 rounding ---------------------------
// src: [E][R][C] fp32 -> dst: [E][C][R] fp16. Grid: (C/32, R/32, E).
__global__ void transpose_w(const float* __restrict__ src, __half* __restrict__ dst,
                            int R, int C) {
    if (threadIdx.x == 0 && threadIdx.y == 0) cudaTriggerProgrammaticLaunchCompletion();
    __shared__ float tile[32][33];
    int e = blockIdx.z;
    src += (size_t)e * R * C;
    dst += (size_t)e * R * C;
    int c0 = blockIdx.x * 32, r0 = blockIdx.y * 32;
    int tx = threadIdx.x, ty = threadIdx.y;
    #pragma unroll
    for (int j = 0; j < 32; j += 8)
        tile[ty + j][tx] = src[(size_t)(r0 + ty + j) * C + c0 + tx];
    __syncthreads();
    #pragma unroll
    for (int j = 0; j < 32; j += 8)
        dst[(size_t)(c0 + ty + j) * R + r0 + tx] = __float2half_rn(tile[tx][ty + j]);
}

// ---------------- fp16 mma.sync GEMM -----------------------------------------
// C[b](TT x ND) = act(A[b](TT x KD) @ Bt[e]^T + bias[e]);  Bt: [E][ND][KD] fp16
// CTA tile 128 x NBT (NBT=128: 8 warps 64x32, 2 CTA/SM; NBT=64: 8 warps 32x32,
// 3 CTA/SM). BK=64 halves, 3-stage cp.async.
// TRIG: fire PDL trigger at block start. GDS: grid-dep-sync first (PDL secondary).
template <int KD, int ND, int NBT, bool RELU, bool OUT_HALF, bool TRIG, bool GDS>
__global__ __launch_bounds__(256, (NBT == 128 ? 2 : 3))
void moe_gemm(const __half* __restrict__ A, const __half* __restrict__ Bt,
              const float* __restrict__ bias, void* __restrict__ Cv) {
    const int tid = threadIdx.x, wid = tid >> 5, lane = tid & 31;
    if (GDS) cudaGridDependencySynchronize();   // prelaunched; wait priors done
    if (TRIG) {
        if (tid == 0) cudaTriggerProgrammaticLaunchCompletion();
    }
    extern __shared__ uint8_t smraw[];
    const int b = blockIdx.z;
    const int e = g_expert[b];
    const int row0 = blockIdx.y * 128;
    const int col0 = blockIdx.x * NBT;

    const __half* Ab = A + (size_t)b * TT * KD;
    const __half* Bb = Bt + (size_t)e * ND * KD;
    const float* biasb = bias + (size_t)e * ND;

    const uint32_t smBase = smem_u32(smraw);
    const int lr = tid >> 3;   // loader row (0..31)
    const int lc = tid & 7;    // loader 16B chunk (0..7) -> 8 halves

    constexpr int NC = KD / 64;
    constexpr uint32_t STAGE = 16384u + (uint32_t)NBT * 128u;  // A 16KB + B NBT*128B
    constexpr int WN = NBT / 32;       // warps along N
    constexpr int MT = NBT / 32;       // m16 tiles per warp (4 for 128, 2 for 64)

    auto issue = [&](int c) {
        if (c < NC) {
            uint32_t sA = smBase + (uint32_t)(c % 3) * STAGE;
            uint32_t sB = sA + 16384u;
            int k0 = c * 64;
            #pragma unroll
            for (int i = 0; i < 4; ++i) {               // A: 128 rows
                int r = lr + 32 * i;
                cp_async16(sA + SWZ((uint32_t)(r * 128 + lc * 16)),
                           Ab + (size_t)(row0 + r) * KD + k0 + lc * 8);
            }
            #pragma unroll
            for (int i = 0; i < NBT / 32; ++i) {        // B: NBT rows
                int r = lr + 32 * i;
                cp_async16(sB + SWZ((uint32_t)(r * 128 + lc * 16)),
                           Bb + (size_t)(col0 + r) * KD + k0 + lc * 8);
            }
        }
        cp_commit();
    };

    issue(0);
    issue(1);

    const int wm = wid / WN;           // warp row index
    const int wn = wid % WN;           // warp col index (32-col tiles)

    // ldmatrix lane addressing
    const int aRow = lane & 15;          // A: row within 16-row tile
    const int aColB = (lane >> 4) * 16;  // A: 16B col half (k 0-7 / 8-15)
    const int bRow = ((lane >> 4) & 1) * 8 + (lane & 7);  // B: n row within 16
    const int bColB = ((lane >> 3) & 1) * 16;             // B: k-half bytes

    float acc[MT][4][4];
    #pragma unroll
    for (int mt = 0; mt < MT; ++mt)
        #pragma unroll
        for (int nt = 0; nt < 4; ++nt)
            #pragma unroll
            for (int k = 0; k < 4; ++k) acc[mt][nt][k] = 0.f;

    #pragma unroll 1
    for (int c = 0; c < NC; ++c) {
        cp_wait1();
        __syncthreads();
        issue(c + 2);

        uint32_t sA = smBase + (uint32_t)(c % 3) * STAGE;
        uint32_t sB = sA + 16384u;

        #pragma unroll
        for (int ks = 0; ks < 4; ++ks) {        // 4 x k16 per 64-half chunk
            uint32_t af[MT][4];
            #pragma unroll
            for (int mt = 0; mt < MT; ++mt) {
                int row = wm * (MT * 16) + mt * 16 + aRow;
                ldsm4(af[mt], sA + SWZ((uint32_t)(row * 128 + ks * 32 + aColB)));
            }
            uint32_t bf[2][4];
            #pragma unroll
            for (int np = 0; np < 2; ++np) {
                int row = wn * 32 + np * 16 + bRow;
                ldsm4(bf[np], sB + SWZ((uint32_t)(row * 128 + ks * 32 + bColB)));
            }
            #pragma unroll
            for (int mt = 0; mt < MT; ++mt)
                #pragma unroll
                for (int nt = 0; nt < 4; ++nt) {
                    const uint32_t* bp = &bf[nt >> 1][(nt & 1) * 2];
                    mma16816(acc[mt][nt], af[mt], bp[0], bp[1]);
                }
        }
    }

    // ---------------- epilogue: bias (+relu) ----------------
    #pragma unroll
    for (int mt = 0; mt < MT; ++mt) {
        #pragma unroll
        for (int nt = 0; nt < 4; ++nt) {
            int col = col0 + wn * 32 + nt * 8 + (lane & 3) * 2;
            float bv0 = __ldg(biasb + col);
            float bv1 = __ldg(biasb + col + 1);
            #pragma unroll
            for (int h = 0; h < 2; ++h) {
                int row = row0 + wm * (MT * 16) + mt * 16 + (lane >> 2) + h * 8;
                float v0 = acc[mt][nt][h * 2 + 0] + bv0;
                float v1 = acc[mt][nt][h * 2 + 1] + bv1;
                if (RELU) { v0 = fmaxf(v0, 0.f); v1 = fmaxf(v1, 0.f); }
                if (OUT_HALF) {
                    __half2* Ch = (__half2*)((__half*)Cv + (size_t)b * TT * ND);
                    Ch[((size_t)row * ND + col) / 2] = __floats2half2_rn(v0, v1);
                } else {
                    float2 u; u.x = v0; u.y = v1;
                    *reinterpret_cast<float2*>((float*)Cv + (size_t)b * TT * ND +
                                               (size_t)row * ND + col) = u;
                }
            }
        }
    }
}

// ---------------- launch -----------------------------------------------------
extern "C" void kernel_launch(void* const* d_in, const int* in_sizes, int n_in,
                              void* d_out, int out_size) {
    const float* x  = (const float*)d_in[0];
    const float* Wp = (const float*)d_in[1];
    const float* bp = (const float*)d_in[2];
    const float* W1 = (const float*)d_in[3];
    const float* b1 = (const float*)d_in[4];
    const float* W2 = (const float*)d_in[5];
    const float* b2 = (const float*)d_in[6];
    float* out = (float*)d_out;

    void *pW1t, *pW2t, *pH, *pX, *pPart;
    cudaGetSymbolAddress(&pW1t, g_W1t);
    cudaGetSymbolAddress(&pW2t, g_W2t);
    cudaGetSymbolAddress(&pH, g_h);
    cudaGetSymbolAddress(&pX, g_x);
    cudaGetSymbolAddress(&pPart, g_part);

    auto gemm1 = moe_gemm<DD, HH, 128, true, true, true, true>;     // GDS + trigger
    auto gemm2 = moe_gemm<HH, DD, 64, false, false, false, false>;  // plain, 128x64@3

    const int SMEM1 = 98304;   // 3 x 32KB
    const int SMEM2 = 73728;   // 3 x 24KB
    cudaFuncSetAttribute(gemm1, cudaFuncAttributeMaxDynamicSharedMemorySize, SMEM1);
    cudaFuncSetAttribute(gemm2, cudaFuncAttributeMaxDynamicSharedMemorySize, SMEM2);
    cudaFuncSetAttribute(gemm1, cudaFuncAttributePreferredSharedMemoryCarveout, 100);
    cudaFuncSetAttribute(gemm2, cudaFuncAttributePreferredSharedMemoryCarveout, 100);

    cudaLaunchAttribute pdl[1];
    pdl[0].id = cudaLaunchAttributeProgrammaticStreamSerialization;
    pdl[0].val.programmaticStreamSerializationAllowed = 1;

    // 1) convert_pool, 512 CTAs (PDL-triggers at start)
    convert_pool<<<dim3(BB, 16), 256>>>(x, (__half2*)pX, (float*)pPart);

    // 2) W1 transpose (PDL secondary: overlaps convert_pool)
    {
        cudaLaunchConfig_t cfg = {};
        cfg.gridDim = dim3(HH / 32, DD / 32, EE);   // C=H, R=D
        cfg.blockDim = dim3(32, 8, 1);
        cfg.attrs = pdl; cfg.numAttrs = 1;
        cudaLaunchKernelEx(&cfg, transpose_w, W1, (__half*)pW1t, DD, HH);
    }

    // 3) router (PDL secondary + GDS: prelaunched during convert/transW1;
    //    triggers at start so GEMM1 prelaunches during its ~3us)
    {
        cudaLaunchConfig_t cfg = {};
        cfg.gridDim = dim3(BB, 1, 1);
        cfg.blockDim = dim3(256, 1, 1);
        cfg.attrs = pdl; cfg.numAttrs = 1;
        cudaLaunchKernelEx(&cfg, router_final,
                           (const float*)pPart, Wp, bp, out + (size_t)BB * TT * DD);
    }

    // 4) GEMM1 (PDL secondary + GDS: staged during router, starts when g_expert
    //    final; triggers at start so trans_W2 overlaps it)
    {
        cudaLaunchConfig_t cfg = {};
        cfg.gridDim = dim3(HH / 128, TT / 128, BB);
        cfg.blockDim = dim3(256, 1, 1);
        cfg.dynamicSmemBytes = SMEM1;
        cfg.attrs = pdl; cfg.numAttrs = 1;
        cudaLaunchKernelEx(&cfg, gemm1,
                           (const __half*)pX, (const __half*)pW1t, b1, (void*)pH);
    }

    // 5) W2 transpose (PDL secondary: runs CONCURRENTLY with tensor-bound GEMM1)
    {
        cudaLaunchConfig_t cfg = {};
        cfg.gridDim = dim3(DD / 32, HH / 32, EE);   // C=D, R=H
        cfg.blockDim = dim3(32, 8, 1);
        cfg.attrs = pdl; cfg.numAttrs = 1;
        cudaLaunchKernelEx(&cfg, transpose_w, W2, (__half*)pW2t, HH, DD);
    }

    // 6) GEMM2 (normal: waits GEMM1 + trans_W2) — 128x64 tiles, 3 CTA/SM:
    //    1024 tiles over 444 slots = 3 rounds (vs 512/296 = 2 rounds of 2x-size)
    gemm2<<<dim3(DD / 64, TT / 128, BB), 256, SMEM2>>>(
        (const __half*)pH, (const __half*)pW2t, b2, (void*)out);
}